// round 1
// baseline (speedup 1.0000x reference)
#include <cuda_runtime.h>

#define QT 32     // q rows per block
#define KT 64     // k rows per tile
#define DH 64     // head dim
#define SEQ 1024
#define NBH 64    // B*H

// smem layout (floats):
//   Qt  [DH][QT+2]   transposed, pre-scaled Q tile
//   Kt  [DH][KT+4]   transposed K tile; reused as Vs[KT][KT+4] (natural layout) in PV phase
//   Sc  [QT][SEQ+1]  full score / weight rows for this q tile
#define QT_P (QT + 2)
#define KT_P (KT + 4)
#define S_P  (SEQ + 1)

__global__ __launch_bounds__(256, 1)
void hata_attn_kernel(const float* __restrict__ Qg_, const float* __restrict__ Kg_,
                      const float* __restrict__ Vg_, const float* __restrict__ bias,
                      float* __restrict__ outO, float* __restrict__ outW) {
    extern __shared__ float sm[];
    float* Qt = sm;                       // DH * QT_P
    float* Kt = Qt + DH * QT_P;           // DH * KT_P (== KT * KT_P for V reuse)
    float* Sc = Kt + DH * KT_P;           // QT * S_P

    const int t  = threadIdx.x;
    const int tx = t & 15;                // 0..15
    const int ty = t >> 4;                // 0..15
    const int bh = blockIdx.y;
    const int qBase = blockIdx.x * QT;
    const float scale = 0.125f;           // 1/sqrt(64)

    const float* Qg = Qg_ + ((size_t)bh * SEQ + qBase) * DH;
    const float* Kg = Kg_ + (size_t)bh * SEQ * DH;
    const float* Vg = Vg_ + (size_t)bh * SEQ * DH;

    // ---- load Q tile, transposed + pre-scaled ----
    for (int idx = t; idx < QT * DH; idx += 256) {
        int r = idx >> 6, d = idx & 63;
        Qt[d * QT_P + r] = Qg[idx] * scale;
    }

    // ---- phase 1: scores = (Q*scale) @ K^T + bias, into Sc ----
    const int q0 = ty * 2;
    const int k0 = tx * 4;
    for (int kt = 0; kt < SEQ / KT; ++kt) {
        __syncthreads();   // prev-tile compute done before overwriting Kt (and Qt ready on iter 0)
        const float* Kgt = Kg + kt * KT * DH;
        for (int idx = t; idx < KT * DH; idx += 256) {
            int r = idx >> 6, d = idx & 63;
            Kt[d * KT_P + r] = Kgt[idx];
        }
        __syncthreads();

        float a00 = 0.f, a01 = 0.f, a02 = 0.f, a03 = 0.f;
        float a10 = 0.f, a11 = 0.f, a12 = 0.f, a13 = 0.f;
        #pragma unroll 16
        for (int d = 0; d < DH; ++d) {
            float2 qv = *(const float2*)&Qt[d * QT_P + q0];
            float4 kv = *(const float4*)&Kt[d * KT_P + k0];
            a00 += qv.x * kv.x; a01 += qv.x * kv.y; a02 += qv.x * kv.z; a03 += qv.x * kv.w;
            a10 += qv.y * kv.x; a11 += qv.y * kv.y; a12 += qv.y * kv.z; a13 += qv.y * kv.w;
        }
        const int kc = kt * KT + k0;
        const float* b0 = bias + (size_t)(qBase + q0) * SEQ + kc;
        const float* b1 = b0 + SEQ;
        float* s0 = &Sc[(q0)     * S_P + kc];
        float* s1 = &Sc[(q0 + 1) * S_P + kc];
        s0[0] = a00 + b0[0]; s0[1] = a01 + b0[1]; s0[2] = a02 + b0[2]; s0[3] = a03 + b0[3];
        s1[0] = a10 + b1[0]; s1[1] = a11 + b1[1]; s1[2] = a12 + b1[2]; s1[3] = a13 + b1[3];
    }
    __syncthreads();

    // ---- phase 2: softmax per row; write normalized weights to gmem, keep in Sc ----
    {
        const int wid = t >> 5, lane = t & 31;
        for (int r = wid; r < QT; r += 8) {
            float* row = &Sc[r * S_P];
            float m = -1e30f;
            for (int j = lane; j < SEQ; j += 32) m = fmaxf(m, row[j]);
            #pragma unroll
            for (int o = 16; o; o >>= 1) m = fmaxf(m, __shfl_xor_sync(0xffffffffu, m, o));
            float ssum = 0.f;
            for (int j = lane; j < SEQ; j += 32) {
                float e = __expf(row[j] - m);
                row[j] = e;
                ssum += e;
            }
            #pragma unroll
            for (int o = 16; o; o >>= 1) ssum += __shfl_xor_sync(0xffffffffu, ssum, o);
            float inv = 1.f / ssum;
            float* wrow = outW + ((size_t)bh * SEQ + qBase + r) * SEQ;
            for (int j = lane; j < SEQ; j += 32) {
                float w = row[j] * inv;
                row[j] = w;
                wrow[j] = w;
            }
        }
    }

    // ---- phase 3: output = W @ V ----
    {
        const int d0 = tx * 4;
        float a00 = 0.f, a01 = 0.f, a02 = 0.f, a03 = 0.f;
        float a10 = 0.f, a11 = 0.f, a12 = 0.f, a13 = 0.f;
        for (int kt = 0; kt < SEQ / KT; ++kt) {
            __syncthreads();   // prev-tile compute (or softmax) done before overwriting Kt/Vs
            const float* Vgt = Vg + kt * KT * DH;
            for (int idx = t; idx < KT * DH; idx += 256) {
                int r = idx >> 6, d = idx & 63;
                Kt[r * KT_P + d] = Vgt[idx];   // natural [kk][d] layout
            }
            __syncthreads();

            const float* w0p = &Sc[(q0)     * S_P + kt * KT];
            const float* w1p = &Sc[(q0 + 1) * S_P + kt * KT];
            #pragma unroll 16
            for (int kk = 0; kk < KT; ++kk) {
                float w0 = w0p[kk];
                float w1 = w1p[kk];
                float4 vv = *(const float4*)&Kt[kk * KT_P + d0];
                a00 += w0 * vv.x; a01 += w0 * vv.y; a02 += w0 * vv.z; a03 += w0 * vv.w;
                a10 += w1 * vv.x; a11 += w1 * vv.y; a12 += w1 * vv.z; a13 += w1 * vv.w;
            }
        }
        float* o0 = outO + ((size_t)bh * SEQ + qBase + q0) * DH + d0;
        *(float4*)o0          = make_float4(a00, a01, a02, a03);
        *(float4*)(o0 + DH)   = make_float4(a10, a11, a12, a13);
    }
}

extern "C" void kernel_launch(void* const* d_in, const int* in_sizes, int n_in,
                              void* d_out, int out_size) {
    const float* Q    = (const float*)d_in[0];
    const float* K    = (const float*)d_in[1];
    const float* V    = (const float*)d_in[2];
    const float* bias = (const float*)d_in[3];
    float* outO = (float*)d_out;
    float* outW = outO + (size_t)NBH * SEQ * DH;

    size_t smem = (size_t)(DH * QT_P + DH * KT_P + QT * S_P) * sizeof(float);
    cudaFuncSetAttribute(hata_attn_kernel,
                         cudaFuncAttributeMaxDynamicSharedMemorySize, (int)smem);
    dim3 grid(SEQ / QT, NBH);
    hata_attn_kernel<<<grid, 256, smem>>>(Q, K, V, bias, outO, outW);
}

// round 2
// speedup vs baseline: 1.0149x; 1.0149x over previous
#include <cuda_runtime.h>

#define QT 32     // q rows per block
#define KT 64     // k rows per tile
#define DH 64     // head dim
#define SEQ 1024
#define NBH 64    // B*H

// smem layout (floats):
//   Qt  [DH][QT+2]   transposed, pre-scaled Q tile
//   Kt  [DH][KT+4]   transposed K tile; reused as Vs[KT][KT+4] (natural layout) in PV phase
//   Sc  [QT][SEQ+1]  full score / weight rows for this q tile
#define QT_P (QT + 2)
#define KT_P (KT + 4)
#define S_P  (SEQ + 1)

__global__ __launch_bounds__(256, 1)
void hata_attn_kernel(const float* __restrict__ Qg_, const float* __restrict__ Kg_,
                      const float* __restrict__ Vg_, const float* __restrict__ bias,
                      float* __restrict__ outO, float* __restrict__ outW) {
    extern __shared__ float sm[];
    float* Qt = sm;                       // DH * QT_P
    float* Kt = Qt + DH * QT_P;           // DH * KT_P (== KT * KT_P for V reuse)
    float* Sc = Kt + DH * KT_P;           // QT * S_P

    const int t  = threadIdx.x;
    const int tx = t & 15;                // 0..15
    const int ty = t >> 4;                // 0..15
    const int bh = blockIdx.y;
    const int qBase = blockIdx.x * QT;
    const float scale = 0.125f;           // 1/sqrt(64)

    const float* Qg = Qg_ + ((size_t)bh * SEQ + qBase) * DH;
    const float* Kg = Kg_ + (size_t)bh * SEQ * DH;
    const float* Vg = Vg_ + (size_t)bh * SEQ * DH;

    // ---- load Q tile, transposed + pre-scaled ----
    for (int idx = t; idx < QT * DH; idx += 256) {
        int r = idx >> 6, d = idx & 63;
        Qt[d * QT_P + r] = Qg[idx] * scale;
    }

    // ---- phase 1: scores = (Q*scale) @ K^T + bias, into Sc ----
    const int q0 = ty * 2;
    const int k0 = tx * 4;
    for (int kt = 0; kt < SEQ / KT; ++kt) {
        __syncthreads();   // prev-tile compute done before overwriting Kt (and Qt ready on iter 0)
        const float* Kgt = Kg + kt * KT * DH;
        for (int idx = t; idx < KT * DH; idx += 256) {
            int r = idx >> 6, d = idx & 63;
            Kt[d * KT_P + r] = Kgt[idx];
        }
        __syncthreads();

        float a00 = 0.f, a01 = 0.f, a02 = 0.f, a03 = 0.f;
        float a10 = 0.f, a11 = 0.f, a12 = 0.f, a13 = 0.f;
        #pragma unroll 16
        for (int d = 0; d < DH; ++d) {
            float2 qv = *(const float2*)&Qt[d * QT_P + q0];
            float4 kv = *(const float4*)&Kt[d * KT_P + k0];
            a00 += qv.x * kv.x; a01 += qv.x * kv.y; a02 += qv.x * kv.z; a03 += qv.x * kv.w;
            a10 += qv.y * kv.x; a11 += qv.y * kv.y; a12 += qv.y * kv.z; a13 += qv.y * kv.w;
        }
        const int kc = kt * KT + k0;
        const float* b0 = bias + (size_t)(qBase + q0) * SEQ + kc;
        const float* b1 = b0 + SEQ;
        float* s0 = &Sc[(q0)     * S_P + kc];
        float* s1 = &Sc[(q0 + 1) * S_P + kc];
        s0[0] = a00 + b0[0]; s0[1] = a01 + b0[1]; s0[2] = a02 + b0[2]; s0[3] = a03 + b0[3];
        s1[0] = a10 + b1[0]; s1[1] = a11 + b1[1]; s1[2] = a12 + b1[2]; s1[3] = a13 + b1[3];
    }
    __syncthreads();

    // ---- phase 2: softmax per row; write normalized weights to gmem, keep in Sc ----
    {
        const int wid = t >> 5, lane = t & 31;
        for (int r = wid; r < QT; r += 8) {
            float* row = &Sc[r * S_P];
            float m = -1e30f;
            for (int j = lane; j < SEQ; j += 32) m = fmaxf(m, row[j]);
            #pragma unroll
            for (int o = 16; o; o >>= 1) m = fmaxf(m, __shfl_xor_sync(0xffffffffu, m, o));
            float ssum = 0.f;
            for (int j = lane; j < SEQ; j += 32) {
                float e = __expf(row[j] - m);
                row[j] = e;
                ssum += e;
            }
            #pragma unroll
            for (int o = 16; o; o >>= 1) ssum += __shfl_xor_sync(0xffffffffu, ssum, o);
            float inv = 1.f / ssum;
            float* wrow = outW + ((size_t)bh * SEQ + qBase + r) * SEQ;
            for (int j = lane; j < SEQ; j += 32) {
                float w = row[j] * inv;
                row[j] = w;
                wrow[j] = w;
            }
        }
    }

    // ---- phase 3: output = W @ V ----
    {
        const int d0 = tx * 4;
        float a00 = 0.f, a01 = 0.f, a02 = 0.f, a03 = 0.f;
        float a10 = 0.f, a11 = 0.f, a12 = 0.f, a13 = 0.f;
        for (int kt = 0; kt < SEQ / KT; ++kt) {
            __syncthreads();   // prev-tile compute (or softmax) done before overwriting Kt/Vs
            const float* Vgt = Vg + kt * KT * DH;
            for (int idx = t; idx < KT * DH; idx += 256) {
                int r = idx >> 6, d = idx & 63;
                Kt[r * KT_P + d] = Vgt[idx];   // natural [kk][d] layout
            }
            __syncthreads();

            const float* w0p = &Sc[(q0)     * S_P + kt * KT];
            const float* w1p = &Sc[(q0 + 1) * S_P + kt * KT];
            #pragma unroll 16
            for (int kk = 0; kk < KT; ++kk) {
                float w0 = w0p[kk];
                float w1 = w1p[kk];
                float4 vv = *(const float4*)&Kt[kk * KT_P + d0];
                a00 += w0 * vv.x; a01 += w0 * vv.y; a02 += w0 * vv.z; a03 += w0 * vv.w;
                a10 += w1 * vv.x; a11 += w1 * vv.y; a12 += w1 * vv.z; a13 += w1 * vv.w;
            }
        }
        float* o0 = outO + ((size_t)bh * SEQ + qBase + q0) * DH + d0;
        *(float4*)o0          = make_float4(a00, a01, a02, a03);
        *(float4*)(o0 + DH)   = make_float4(a10, a11, a12, a13);
    }
}

extern "C" void kernel_launch(void* const* d_in, const int* in_sizes, int n_in,
                              void* d_out, int out_size) {
    const float* Q    = (const float*)d_in[0];
    const float* K    = (const float*)d_in[1];
    const float* V    = (const float*)d_in[2];
    const float* bias = (const float*)d_in[3];
    float* outO = (float*)d_out;
    float* outW = outO + (size_t)NBH * SEQ * DH;

    size_t smem = (size_t)(DH * QT_P + DH * KT_P + QT * S_P) * sizeof(float);
    cudaFuncSetAttribute(hata_attn_kernel,
                         cudaFuncAttributeMaxDynamicSharedMemorySize, (int)smem);
    dim3 grid(SEQ / QT, NBH);
    hata_attn_kernel<<<grid, 256, smem>>>(Q, K, V, bias, outO, outW);
}

// round 5
// speedup vs baseline: 3.3379x; 3.2888x over previous
#include <cuda_runtime.h>
#include <cuda_bf16.h>
#include <cstdint>

#define SEQ 1024
#define DH  64
#define NBH 64
#define MT  128
#define NC  128

#define S1  144   // row stride (bytes) for 64-col bf16 tiles (128B data + 16 pad)
#define S2  272   // row stride (bytes) for 128-col bf16 tiles (256B data + 16 pad)

// smem offsets (bytes)
#define P1_QH 0
#define P1_QL 18432
#define P1_KH 36864
#define P1_KL 55296
#define P2_WH 0
#define P2_WL 34816
#define P2_VH 69632
#define P2_VL 87040
#define ST_SUM 104448            // 128*8 floats
#define ST_INV (104448 + 4096)   // 128 floats
#define SMEM_TOTAL (104448 + 4096 + 512)

__device__ __forceinline__ uint32_t sm_u32(const void* p) {
    uint32_t a;
    asm("{ .reg .u64 t; cvta.to.shared.u64 t, %1; cvt.u32.u64 %0, t; }" : "=r"(a) : "l"(p));
    return a;
}
__device__ __forceinline__ uint32_t pack2(__nv_bfloat16 a, __nv_bfloat16 b) {
    return (uint32_t)__bfloat16_as_ushort(a) | ((uint32_t)__bfloat16_as_ushort(b) << 16);
}
__device__ __forceinline__ void split4(float4 v, uint2& h, uint2& l) {
    __nv_bfloat16 h0 = __float2bfloat16(v.x), h1 = __float2bfloat16(v.y);
    __nv_bfloat16 h2 = __float2bfloat16(v.z), h3 = __float2bfloat16(v.w);
    __nv_bfloat16 l0 = __float2bfloat16(v.x - __bfloat162float(h0));
    __nv_bfloat16 l1 = __float2bfloat16(v.y - __bfloat162float(h1));
    __nv_bfloat16 l2 = __float2bfloat16(v.z - __bfloat162float(h2));
    __nv_bfloat16 l3 = __float2bfloat16(v.w - __bfloat162float(h3));
    h.x = pack2(h0, h1); h.y = pack2(h2, h3);
    l.x = pack2(l0, l1); l.y = pack2(l2, l3);
}

#define LDSM4(a, addr) \
    asm volatile("ldmatrix.sync.aligned.m8n8.x4.shared.b16 {%0,%1,%2,%3}, [%4];" \
        : "=r"((a)[0]), "=r"((a)[1]), "=r"((a)[2]), "=r"((a)[3]) : "r"(addr))
#define LDSM2(b, addr) \
    asm volatile("ldmatrix.sync.aligned.m8n8.x2.shared.b16 {%0,%1}, [%2];" \
        : "=r"((b)[0]), "=r"((b)[1]) : "r"(addr))

__device__ __forceinline__ void mma_bf16(float* c, const uint32_t* a, const uint32_t* b) {
    asm volatile("mma.sync.aligned.m16n8k16.row.col.f32.bf16.bf16.f32 "
        "{%0,%1,%2,%3}, {%4,%5,%6,%7}, {%8,%9}, {%0,%1,%2,%3};"
        : "+f"(c[0]), "+f"(c[1]), "+f"(c[2]), "+f"(c[3])
        : "r"(a[0]), "r"(a[1]), "r"(a[2]), "r"(a[3]), "r"(b[0]), "r"(b[1]));
}

__global__ __launch_bounds__(256, 1)
void attn_fused(const float* __restrict__ Qg, const float* __restrict__ Kg,
                const float* __restrict__ Vg, const float* __restrict__ bias,
                float* __restrict__ outO, float* __restrict__ outW)
{
    extern __shared__ char sm[];
    const uint32_t sb = sm_u32(sm);
    const int tid = threadIdx.x;
    const int lane = tid & 31, wid = tid >> 5;
    const int gid = lane >> 2, tig = lane & 3;
    const int wm = wid >> 1, wn = wid & 1;
    const int bh = blockIdx.y, qb = blockIdx.x * MT;

    // ---- convert Q tile (pre-scaled, hi/lo split) ----
    {
        const float* Qp = Qg + ((size_t)bh * SEQ + qb) * DH;
        int r = tid >> 1, c0 = (tid & 1) * 32;
        #pragma unroll
        for (int j = 0; j < 8; ++j) {
            float4 v = *(const float4*)(Qp + r * DH + c0 + j * 4);
            v.x *= 0.125f; v.y *= 0.125f; v.z *= 0.125f; v.w *= 0.125f;
            uint2 h, l; split4(v, h, l);
            *(uint2*)(sm + P1_QH + r * S1 + (c0 + j * 4) * 2) = h;
            *(uint2*)(sm + P1_QL + r * S1 + (c0 + j * 4) * 2) = l;
        }
    }
    __syncthreads();

    // ---- preload Q fragments (constant over chunks) ----
    uint32_t aqh[4][2][4], aql[4][2][4];
    #pragma unroll
    for (int kt = 0; kt < 4; ++kt)
        #pragma unroll
        for (int mi = 0; mi < 2; ++mi) {
            uint32_t ra = sb + P1_QH + (uint32_t)((wm * 32 + mi * 16 + (lane & 15)) * S1
                         + (lane >> 4) * 16 + kt * 32);
            LDSM4(aqh[kt][mi], ra);
            LDSM4(aql[kt][mi], ra + (P1_QL - P1_QH));
        }

    float rs[2][2] = {{0.f, 0.f}, {0.f, 0.f}};

    // ================= phase 1: raw scores + row exp-sums =================
    for (int nc = 0; nc < 8; ++nc) {
        __syncthreads();
        {   // convert K chunk
            const float* Kp = Kg + ((size_t)bh * SEQ + nc * NC) * DH;
            int r = tid >> 1, c0 = (tid & 1) * 32;
            #pragma unroll
            for (int j = 0; j < 8; ++j) {
                float4 v = *(const float4*)(Kp + r * DH + c0 + j * 4);
                uint2 h, l; split4(v, h, l);
                *(uint2*)(sm + P1_KH + r * S1 + (c0 + j * 4) * 2) = h;
                *(uint2*)(sm + P1_KL + r * S1 + (c0 + j * 4) * 2) = l;
            }
        }
        __syncthreads();

        float acc[2][8][4];
        #pragma unroll
        for (int mi = 0; mi < 2; ++mi)
            #pragma unroll
            for (int ni = 0; ni < 8; ++ni)
                #pragma unroll
                for (int e = 0; e < 4; ++e) acc[mi][ni][e] = 0.f;

        #pragma unroll
        for (int kt = 0; kt < 4; ++kt) {
            #pragma unroll
            for (int ni = 0; ni < 8; ++ni) {
                uint32_t addr = sb + P1_KH + (uint32_t)((wn * 64 + ni * 8 + (lane & 7)) * S1
                               + ((lane >> 3) & 1) * 16 + kt * 32);
                uint32_t bh2[2], bl2[2];
                LDSM2(bh2, addr);
                LDSM2(bl2, addr + (P1_KL - P1_KH));
                #pragma unroll
                for (int mi = 0; mi < 2; ++mi) {
                    mma_bf16(acc[mi][ni], aqh[kt][mi], bh2);
                    mma_bf16(acc[mi][ni], aqh[kt][mi], bl2);
                    mma_bf16(acc[mi][ni], aql[kt][mi], bh2);
                }
            }
        }
        // epilogue: + bias, store raw scores, accumulate exp-sums
        #pragma unroll
        for (int mi = 0; mi < 2; ++mi) {
            int r0 = qb + wm * 32 + mi * 16 + gid;
            #pragma unroll
            for (int ni = 0; ni < 8; ++ni) {
                int c = nc * NC + wn * 64 + ni * 8 + tig * 2;
                float2 b0 = *(const float2*)(bias + (size_t)r0 * SEQ + c);
                float s0 = acc[mi][ni][0] + b0.x, s1 = acc[mi][ni][1] + b0.y;
                *(float2*)(outW + ((size_t)bh * SEQ + r0) * SEQ + c) = make_float2(s0, s1);
                rs[mi][0] += __expf(s0) + __expf(s1);
                float2 b1 = *(const float2*)(bias + (size_t)(r0 + 8) * SEQ + c);
                float s2 = acc[mi][ni][2] + b1.x, s3 = acc[mi][ni][3] + b1.y;
                *(float2*)(outW + ((size_t)bh * SEQ + r0 + 8) * SEQ + c) = make_float2(s2, s3);
                rs[mi][1] += __expf(s2) + __expf(s3);
            }
        }
    }

    // ---- reduce per-row exp sums -> 1/sum ----
    {
        float* st = (float*)(sm + ST_SUM);
        int slot = wn * 4 + tig;
        #pragma unroll
        for (int mi = 0; mi < 2; ++mi)
            #pragma unroll
            for (int h = 0; h < 2; ++h) {
                int r = wm * 32 + mi * 16 + h * 8 + gid;
                st[r * 8 + slot] = rs[mi][h];
            }
    }
    __syncthreads();
    if (tid < 128) {
        float* st = (float*)(sm + ST_SUM);
        float s = 0.f;
        #pragma unroll
        for (int i = 0; i < 8; ++i) s += st[tid * 8 + i];
        ((float*)(sm + ST_INV))[tid] = 1.f / s;
    }

    // ================= phase 2: normalize W + O = W@V =================
    float accO[2][4][4];
    #pragma unroll
    for (int mi = 0; mi < 2; ++mi)
        #pragma unroll
        for (int ni = 0; ni < 4; ++ni)
            #pragma unroll
            for (int e = 0; e < 4; ++e) accO[mi][ni][e] = 0.f;

    const float* sInv = (const float*)(sm + ST_INV);

    for (int nc = 0; nc < 8; ++nc) {
        __syncthreads();
        {   // normalize W chunk (in place) + split to smem A-tile
            int r = tid >> 1, c0 = (tid & 1) * 64;
            float inv = sInv[r];
            float* Wp = outW + ((size_t)bh * SEQ + qb + r) * SEQ + nc * NC + c0;
            #pragma unroll
            for (int j = 0; j < 16; ++j) {
                float4 s = *(float4*)(Wp + j * 4);
                float4 w = make_float4(__expf(s.x) * inv, __expf(s.y) * inv,
                                       __expf(s.z) * inv, __expf(s.w) * inv);
                *(float4*)(Wp + j * 4) = w;
                uint2 h, l; split4(w, h, l);
                *(uint2*)(sm + P2_WH + r * S2 + (c0 + j * 4) * 2) = h;
                *(uint2*)(sm + P2_WL + r * S2 + (c0 + j * 4) * 2) = l;
            }
        }
        {   // V chunk -> transposed split smem [d][s]
            int s0 = (tid & 63) * 2, d0 = (tid >> 6) * 16;
            const float* vp = Vg + ((size_t)bh * SEQ + nc * NC + s0) * DH + d0;
            float va[16], vb[16];
            #pragma unroll
            for (int j = 0; j < 4; ++j) {
                *(float4*)(va + j * 4) = *(const float4*)(vp + j * 4);
                *(float4*)(vb + j * 4) = *(const float4*)(vp + DH + j * 4);
            }
            #pragma unroll
            for (int d = 0; d < 16; ++d) {
                __nv_bfloat16 ha = __float2bfloat16(va[d]);
                __nv_bfloat16 hb = __float2bfloat16(vb[d]);
                __nv_bfloat16 la = __float2bfloat16(va[d] - __bfloat162float(ha));
                __nv_bfloat16 lb = __float2bfloat16(vb[d] - __bfloat162float(hb));
                *(uint32_t*)(sm + P2_VH + (d0 + d) * S2 + s0 * 2) = pack2(ha, hb);
                *(uint32_t*)(sm + P2_VL + (d0 + d) * S2 + s0 * 2) = pack2(la, lb);
            }
        }
        __syncthreads();

        #pragma unroll
        for (int kt = 0; kt < 8; ++kt) {
            uint32_t awh[2][4], awl[2][4];
            #pragma unroll
            for (int mi = 0; mi < 2; ++mi) {
                uint32_t ra = sb + P2_WH + (uint32_t)((wm * 32 + mi * 16 + (lane & 15)) * S2
                             + (lane >> 4) * 16 + kt * 32);
                LDSM4(awh[mi], ra);
                LDSM4(awl[mi], ra + (P2_WL - P2_WH));
            }
            #pragma unroll
            for (int ni = 0; ni < 4; ++ni) {
                uint32_t addr = sb + P2_VH + (uint32_t)((wn * 32 + ni * 8 + (lane & 7)) * S2
                               + ((lane >> 3) & 1) * 16 + kt * 32);
                uint32_t bh2[2], bl2[2];
                LDSM2(bh2, addr);
                LDSM2(bl2, addr + (P2_VL - P2_VH));
                #pragma unroll
                for (int mi = 0; mi < 2; ++mi) {
                    mma_bf16(accO[mi][ni], awh[mi], bh2);
                    mma_bf16(accO[mi][ni], awh[mi], bl2);
                    mma_bf16(accO[mi][ni], awl[mi], bh2);
                }
            }
        }
    }

    // ---- O epilogue ----
    #pragma unroll
    for (int mi = 0; mi < 2; ++mi) {
        int r0 = qb + wm * 32 + mi * 16 + gid;
        #pragma unroll
        for (int ni = 0; ni < 4; ++ni) {
            int c = wn * 32 + ni * 8 + tig * 2;
            *(float2*)(outO + ((size_t)bh * SEQ + r0) * DH + c) =
                make_float2(accO[mi][ni][0], accO[mi][ni][1]);
            *(float2*)(outO + ((size_t)bh * SEQ + r0 + 8) * DH + c) =
                make_float2(accO[mi][ni][2], accO[mi][ni][3]);
        }
    }
}

extern "C" void kernel_launch(void* const* d_in, const int* in_sizes, int n_in,
                              void* d_out, int out_size) {
    const float* Q    = (const float*)d_in[0];
    const float* K    = (const float*)d_in[1];
    const float* V    = (const float*)d_in[2];
    const float* bias = (const float*)d_in[3];
    float* outO = (float*)d_out;
    float* outW = outO + (size_t)NBH * SEQ * DH;

    static int inited = 0;
    if (!inited) {
        cudaFuncSetAttribute(attn_fused, cudaFuncAttributeMaxDynamicSharedMemorySize, SMEM_TOTAL);
        inited = 1;
    }
    dim3 grid(SEQ / MT, NBH);
    attn_fused<<<grid, 256, SMEM_TOTAL>>>(Q, K, V, bias, outO, outW);
}